// round 3
// baseline (speedup 1.0000x reference)
#include <cuda_runtime.h>
#include <cuda_bf16.h>
#include <cstdint>

// Problem constants
#define NN    10000
#define EE    320000
#define BB    64
#define IN_C  128
#define EC    64
#define HID   256
#define MLPD  512
#define NCO   4
#define EPSV  1e-5f
#define MAXSZ 40.0f

// ---------------- scratch ----------------
__device__ int   g_deg[NN];
__device__ int   g_off[NN + 2];
__device__ int   g_cur[NN];
__device__ int   g_src[EE];
__device__ int   g_eid[EE];
__device__ __align__(16) float g_Sea[NN * EC];
__device__ __align__(16) float g_S[NN * HID];    // neighbor sums (incl. self)
__device__ __align__(16) float g_h[NN * HID];    // post-BN activation
__device__ __align__(16) float g_hp[NN * HID];   // post-relu pre-BN
__device__ float g_stats3[3 * 2 * HID];          // [layer][sum(256) | sumsq(256)]

// ---------------- init ----------------
__global__ void zero_init_kernel() {
    int i = blockIdx.x * blockDim.x + threadIdx.x;
    if (i < NN) g_deg[i] = 0;
    if (i < 3 * 2 * HID) g_stats3[i] = 0.f;
}

// ---------------- CSR build ----------------
__global__ void hist_kernel(const int* __restrict__ ei) {
    int e = blockIdx.x * blockDim.x + threadIdx.x;
    if (e < EE) atomicAdd(&g_deg[ei[EE + e]], 1);
}

__global__ void scan_kernel() {
    const int CH = 10;
    int tid = threadIdx.x;
    int base = tid * CH;
    int local[CH];
    int s = 0;
#pragma unroll
    for (int i = 0; i < CH; i++) {
        int idx = base + i;
        int v = (idx < NN) ? g_deg[idx] : 0;
        local[i] = s;
        s += v;
    }
    __shared__ int sh[1024];
    sh[tid] = s;
    __syncthreads();
    for (int d = 1; d < 1024; d <<= 1) {
        int t = (tid >= d) ? sh[tid - d] : 0;
        __syncthreads();
        sh[tid] += t;
        __syncthreads();
    }
    int excl = sh[tid] - s;
#pragma unroll
    for (int i = 0; i < CH; i++) {
        int idx = base + i;
        if (idx < NN) {
            int o = excl + local[i];
            g_off[idx] = o;
            g_cur[idx] = o;
        }
    }
    if (tid == 0) { g_off[NN] = EE; g_off[NN + 1] = EE; }
}

__global__ void fill_kernel(const int* __restrict__ ei) {
    int e = blockIdx.x * blockDim.x + threadIdx.x;
    if (e < EE) {
        int s = ei[e];
        int d = ei[EE + e];
        int pos = atomicAdd(&g_cur[d], 1);
        g_src[pos] = s;
        g_eid[pos] = e;
    }
}

// ---------------- Sea (edge-attr sums; self-loop attr = 1.0) ----------------
__global__ void sea_kernel(const float* __restrict__ ea) {
    int v = blockIdx.x;
    int t = threadIdx.x;  // 64
    int s0 = g_off[v], s1 = g_off[v + 1];
    float acc = 1.0f;
    for (int j = s0; j < s1; j++) acc += ea[g_eid[j] * EC + t];
    g_Sea[v * EC + t] = acc;
}

// ---------------- neighbor-sum aggregation: S[v] = h[v] + sum_src h[src] ----------------
template <int D, bool USE_G>
__global__ void agg_kernel(const float* __restrict__ xin) {
    const float* __restrict__ hin = USE_G ? (const float*)g_h : xin;
    int v = blockIdx.x;
    int t = threadIdx.x;  // D threads
    int s0 = g_off[v], s1 = g_off[v + 1];
    float acc = hin[v * D + t];
    int j = s0;
    for (; j + 4 <= s1; j += 4) {
        int a = g_src[j], b = g_src[j + 1], c = g_src[j + 2], d = g_src[j + 3];
        acc += hin[a * D + t] + hin[b * D + t] + hin[c * D + t] + hin[d * D + t];
    }
    for (; j < s1; j++) acc += hin[g_src[j] * D + t];
    g_S[v * D + t] = acc;
}

// ---------------- 3xTF32 tensor-core GEMM with fused bias/relu/stats ----------------
// C[row, col] = relu( deg*h @ W[0:D] + S @ W[D:2D] + Sea @ W[2D:2D+EC] + deg*b )
// BM=128 BN=64 BK=16, 256 threads (8 warps as 4x2), warp tile 32x32 (m16n8k8 x 2x4)

__device__ __forceinline__ uint32_t f2tf32(float x) {
    uint32_t r;
    asm("cvt.rna.tf32.f32 %0, %1;" : "=r"(r) : "f"(x));
    return r;
}

__device__ __forceinline__ void mma_tf32(float* c, const uint32_t* a, const uint32_t* b) {
    asm volatile(
        "mma.sync.aligned.m16n8k8.row.col.f32.tf32.tf32.f32 "
        "{%0,%1,%2,%3}, {%4,%5,%6,%7}, {%8,%9}, {%0,%1,%2,%3};\n"
        : "+f"(c[0]), "+f"(c[1]), "+f"(c[2]), "+f"(c[3])
        : "r"(a[0]), "r"(a[1]), "r"(a[2]), "r"(a[3]), "r"(b[0]), "r"(b[1]));
}

template <int D, bool USE_G>
__global__ __launch_bounds__(256) void gemm3_kernel(const float* __restrict__ xin,
                                                    const float* __restrict__ W,
                                                    const float* __restrict__ bias,
                                                    int layer) {
    const int K = 2 * D + EC;
    const int NTILE = K / 16;
    const float* __restrict__ hin = USE_G ? (const float*)g_h : xin;

    __shared__ uint32_t AH[2048], AL[2048];  // [tm(8)][k8(2)][lane(32)][4]
    __shared__ uint32_t BH[1024], BL[1024];  // [tn(8)][k8(2)][lane(32)][2]
    __shared__ float s_deg[128], s_bias[64], s_sum[64], s_sq[64];

    int tid = threadIdx.x;
    int lane = tid & 31;
    int wid = tid >> 5;
    int warp_m = wid >> 1;  // 0..3
    int warp_n = wid & 1;   // 0..1
    int rowBase = blockIdx.y * 128;
    int colBase = blockIdx.x * 64;

    if (tid < 128) {
        int r = rowBase + tid;
        s_deg[tid] = (r < NN) ? (float)(g_off[r + 1] - g_off[r] + 1) : 0.f;
    }
    if (tid < 64) {
        s_bias[tid] = bias[colBase + tid];
        s_sum[tid] = 0.f;
        s_sq[tid] = 0.f;
    }
    __syncthreads();

    float acc[2][4][4];
#pragma unroll
    for (int i = 0; i < 2; i++)
#pragma unroll
        for (int j = 0; j < 4; j++)
#pragma unroll
            for (int q = 0; q < 4; q++) acc[i][j][q] = 0.f;

    // A staging map: thread -> row = tid/2, k-offset ak = (tid&1)*8
    int arow = tid >> 1;
    int ak = (tid & 1) * 8;
    int grow = rowBase + arow;
    bool avalid = grow < NN;
    float degv = s_deg[arow];
    // B staging map: thread -> k-row = tid/16 (0..15), col = (tid%16)*4
    int brow = tid >> 4;
    int bcol = (tid & 15) * 4;

    float4 pa0, pa1, pb;

    auto load_tile = [&](int kt, float4& A0, float4& A1, float4& Bv) {
        int kg = kt * 16;
        if (avalid) {
            const float* ap;
            float sc = 1.f;
            if (kg < D) {
                ap = hin + (size_t)grow * D + kg + ak;
                sc = degv;
            } else if (kg < 2 * D) {
                ap = g_S + (size_t)grow * D + (kg - D) + ak;
            } else {
                ap = g_Sea + (size_t)grow * EC + (kg - 2 * D) + ak;
            }
            A0 = *(const float4*)ap;
            A1 = *(const float4*)(ap + 4);
            A0.x *= sc; A0.y *= sc; A0.z *= sc; A0.w *= sc;
            A1.x *= sc; A1.y *= sc; A1.z *= sc; A1.w *= sc;
        } else {
            A0 = make_float4(0.f, 0.f, 0.f, 0.f);
            A1 = A0;
        }
        Bv = *(const float4*)&W[(size_t)(kg + brow) * HID + colBase + bcol];
    };

    auto store_tile = [&](const float4& A0, const float4& A1, const float4& Bv) {
        // A: elements (m=arow, k_local = ak + e) e=0..7
        int k8 = (tid & 1);  // ak/8
        int tm = arow >> 4;
        int mbit = (arow >> 3) & 1;
        int lbase = (arow & 7) * 4;
        int tilebase = ((tm * 2 + k8) * 32) * 4;
        float av[8] = {A0.x, A0.y, A0.z, A0.w, A1.x, A1.y, A1.z, A1.w};
#pragma unroll
        for (int e = 0; e < 8; e++) {
            int kk = e;  // k within 8
            int ln = lbase + (kk & 3);
            int r = ((kk >= 4) ? 2 : 0) + mbit;
            int idx = tilebase + ln * 4 + r;
            uint32_t hi = f2tf32(av[e]);
            float hif = __uint_as_float(hi);
            uint32_t lo = f2tf32(av[e] - hif);
            AH[idx] = hi;
            AL[idx] = lo;
        }
        // B: elements (k=brow, n = bcol + e)
        int bk8 = brow >> 3;
        int bkk = brow & 7;
        float bv[4] = {Bv.x, Bv.y, Bv.z, Bv.w};
#pragma unroll
        for (int e = 0; e < 4; e++) {
            int n = bcol + e;
            int tn = n >> 3;
            int ln = (n & 7) * 4 + (bkk & 3);
            int r = (bkk >= 4) ? 1 : 0;
            int idx = ((tn * 2 + bk8) * 32 + ln) * 2 + r;
            uint32_t hi = f2tf32(bv[e]);
            float hif = __uint_as_float(hi);
            uint32_t lo = f2tf32(bv[e] - hif);
            BH[idx] = hi;
            BL[idx] = lo;
        }
    };

    load_tile(0, pa0, pa1, pb);

    for (int kt = 0; kt < NTILE; kt++) {
        __syncthreads();  // prior tile's mma done
        store_tile(pa0, pa1, pb);
        __syncthreads();
        if (kt + 1 < NTILE) load_tile(kt + 1, pa0, pa1, pb);

#pragma unroll
        for (int k8 = 0; k8 < 2; k8++) {
            uint32_t fah[2][4], fal[2][4];
            uint32_t fbh[4][2], fbl[4][2];
#pragma unroll
            for (int i = 0; i < 2; i++) {
                int tm = warp_m * 2 + i;
                int base = ((tm * 2 + k8) * 32 + lane) * 4;
                *(uint4*)fah[i] = *(const uint4*)&AH[base];
                *(uint4*)fal[i] = *(const uint4*)&AL[base];
            }
#pragma unroll
            for (int j = 0; j < 4; j++) {
                int tn = warp_n * 4 + j;
                int base = ((tn * 2 + k8) * 32 + lane) * 2;
                *(uint2*)fbh[j] = *(const uint2*)&BH[base];
                *(uint2*)fbl[j] = *(const uint2*)&BL[base];
            }
#pragma unroll
            for (int i = 0; i < 2; i++)
#pragma unroll
                for (int j = 0; j < 4; j++) {
                    mma_tf32(acc[i][j], fah[i], fbh[j]);
                    mma_tf32(acc[i][j], fal[i], fbh[j]);
                    mma_tf32(acc[i][j], fah[i], fbl[j]);
                }
        }
    }

    // ---------- epilogue: bias, relu, store, stats ----------
    int r0 = lane >> 2;
    int c4 = lane & 3;
#pragma unroll
    for (int j = 0; j < 4; j++) {
        int col_l = warp_n * 32 + j * 8 + c4 * 2;
        float b0 = s_bias[col_l], b1 = s_bias[col_l + 1];
        float ss0 = 0.f, ss1 = 0.f, q0 = 0.f, q1 = 0.f;
#pragma unroll
        for (int i = 0; i < 2; i++) {
            int row_l = warp_m * 32 + i * 16 + r0;
            int gr0 = rowBase + row_l;
            int gr1 = gr0 + 8;
            bool v0 = gr0 < NN, v1 = gr1 < NN;
            float d0 = s_deg[row_l], d1 = s_deg[row_l + 8];
            float x00 = fmaxf(acc[i][j][0] + d0 * b0, 0.f);
            float x01 = fmaxf(acc[i][j][1] + d0 * b1, 0.f);
            float x10 = fmaxf(acc[i][j][2] + d1 * b0, 0.f);
            float x11 = fmaxf(acc[i][j][3] + d1 * b1, 0.f);
            if (v0) *(float2*)&g_hp[(size_t)gr0 * HID + colBase + col_l] = make_float2(x00, x01);
            if (v1) *(float2*)&g_hp[(size_t)gr1 * HID + colBase + col_l] = make_float2(x10, x11);
            float m00 = v0 ? x00 : 0.f, m01 = v0 ? x01 : 0.f;
            float m10 = v1 ? x10 : 0.f, m11 = v1 ? x11 : 0.f;
            ss0 += m00 + m10;
            ss1 += m01 + m11;
            q0 += m00 * m00 + m10 * m10;
            q1 += m01 * m01 + m11 * m11;
        }
        // reduce across the 8 lanes sharing this column set (same lane%4)
#pragma unroll
        for (int o = 4; o < 32; o <<= 1) {
            ss0 += __shfl_xor_sync(0xffffffffu, ss0, o);
            ss1 += __shfl_xor_sync(0xffffffffu, ss1, o);
            q0 += __shfl_xor_sync(0xffffffffu, q0, o);
            q1 += __shfl_xor_sync(0xffffffffu, q1, o);
        }
        if (lane < 4) {
            int cl = warp_n * 32 + j * 8 + lane * 2;
            atomicAdd(&s_sum[cl], ss0);
            atomicAdd(&s_sum[cl + 1], ss1);
            atomicAdd(&s_sq[cl], q0);
            atomicAdd(&s_sq[cl + 1], q1);
        }
    }
    __syncthreads();
    if (tid < 64) {
        atomicAdd(&g_stats3[layer * 512 + colBase + tid], s_sum[tid]);
        atomicAdd(&g_stats3[layer * 512 + HID + colBase + tid], s_sq[tid]);
    }
}

// ---------------- BN apply + relu -> g_h ----------------
__global__ void bn_kernel(const float* __restrict__ gamma, const float* __restrict__ beta,
                          int layer) {
    int idx = blockIdx.x * blockDim.x + threadIdx.x;
    if (idx >= NN * HID / 4) return;
    int f = idx * 4;
    int c = f & (HID - 1);
    const float invN = 1.0f / (float)NN;
    float4 v = *(const float4*)&g_hp[f];
    float4 o;
#pragma unroll
    for (int e = 0; e < 4; e++) {
        int cc = c + e;
        float mu = g_stats3[layer * 512 + cc] * invN;
        float var = g_stats3[layer * 512 + HID + cc] * invN - mu * mu;
        float rs = rsqrtf(var + EPSV);
        float val = ((&v.x)[e] - mu) * rs * gamma[cc] + beta[cc];
        (&o.x)[e] = fmaxf(val, 0.f);
    }
    *(float4*)&g_h[f] = o;
}

// ---------------- fused: layer-3 BN + pooling + MLP ----------------
__device__ __forceinline__ int lower_bound_dev(const int* a, int n, int key) {
    int lo = 0, hi = n;
    while (lo < hi) {
        int m = (lo + hi) >> 1;
        if (a[m] < key) lo = m + 1; else hi = m;
    }
    return lo;
}

__global__ __launch_bounds__(512) void mlp_kernel(const int* __restrict__ batch,
                                                  const float* __restrict__ neighbor,
                                                  const float* __restrict__ g3,
                                                  const float* __restrict__ be3,
                                                  const float* __restrict__ fc1w,
                                                  const float* __restrict__ fc1b,
                                                  const float* __restrict__ fc2w,
                                                  const float* __restrict__ fc2b,
                                                  float* __restrict__ out) {
    const int ZD = HID + 1 + IN_C;  // 385
    __shared__ float z[ZD];
    __shared__ float part[512];
    __shared__ float red[NCO];
    int b = blockIdx.x;
    int t = threadIdx.x;

    int lo = lower_bound_dev(batch, NN, b);
    int hi = lower_bound_dev(batch, NN, b + 1);

    // pooling with inline layer-3 BN + relu
    {
        int c = t & 255;
        int half = t >> 8;
        const float invN = 1.0f / (float)NN;
        float mu = g_stats3[2 * 512 + c] * invN;
        float var = g_stats3[2 * 512 + HID + c] * invN - mu * mu;
        float rs = rsqrtf(var + EPSV);
        float sc = g3[c] * rs;
        float off = be3[c] - mu * sc;
        float s = 0.f;
        for (int r = lo + half; r < hi; r += 2)
            s += fmaxf(g_hp[(size_t)r * HID + c] * sc + off, 0.f);
        part[t] = s;
    }
    __syncthreads();
    if (t < HID) z[t] = part[t] + part[t + 256];
    else if (t == HID) z[HID] = (float)(hi - lo) / MAXSZ;
    else if (t < HID + 1 + IN_C + 1 && t > HID) {
        int k = t - HID - 1;
        if (k < IN_C) z[HID + 1 + k] = neighbor[b * IN_C + k];
    }
    if (t < NCO) red[t] = fc2b[t];
    __syncthreads();

    // fc1 + relu
    float acc = fc1b[t];
#pragma unroll 4
    for (int k = 0; k < ZD; k++) acc += z[k] * fc1w[k * MLPD + t];
    float h1 = fmaxf(acc, 0.f);

    // fc2: warp reduce then smem atomic
    float4 w4 = *(const float4*)&fc2w[t * NCO];
    float p0 = h1 * w4.x, p1 = h1 * w4.y, p2 = h1 * w4.z, p3 = h1 * w4.w;
#pragma unroll
    for (int o = 16; o >= 1; o >>= 1) {
        p0 += __shfl_xor_sync(0xffffffffu, p0, o);
        p1 += __shfl_xor_sync(0xffffffffu, p1, o);
        p2 += __shfl_xor_sync(0xffffffffu, p2, o);
        p3 += __shfl_xor_sync(0xffffffffu, p3, o);
    }
    if ((t & 31) == 0) {
        atomicAdd(&red[0], p0);
        atomicAdd(&red[1], p1);
        atomicAdd(&red[2], p2);
        atomicAdd(&red[3], p3);
    }
    __syncthreads();
    if (t < NCO) out[b * NCO + t] = red[t];
}

// ---------------- launch ----------------
extern "C" void kernel_launch(void* const* d_in, const int* in_sizes, int n_in,
                              void* d_out, int out_size) {
    const float* x        = (const float*)d_in[0];
    const int*   ei       = (const int*)d_in[1];
    const float* ea       = (const float*)d_in[2];
    const int*   batch    = (const int*)d_in[3];
    const float* neighbor = (const float*)d_in[4];
    const float* W1  = (const float*)d_in[5];
    const float* b1  = (const float*)d_in[6];
    const float* g1  = (const float*)d_in[7];
    const float* be1 = (const float*)d_in[8];
    const float* W2  = (const float*)d_in[9];
    const float* b2  = (const float*)d_in[10];
    const float* g2  = (const float*)d_in[11];
    const float* be2 = (const float*)d_in[12];
    const float* W3  = (const float*)d_in[13];
    const float* b3  = (const float*)d_in[14];
    const float* g3  = (const float*)d_in[15];
    const float* be3 = (const float*)d_in[16];
    const float* fc1w = (const float*)d_in[17];
    const float* fc1b = (const float*)d_in[18];
    const float* fc2w = (const float*)d_in[19];
    const float* fc2b = (const float*)d_in[20];
    float* out = (float*)d_out;

    zero_init_kernel<<<(NN + 255) / 256, 256>>>();
    hist_kernel<<<(EE + 255) / 256, 256>>>(ei);
    scan_kernel<<<1, 1024>>>();
    fill_kernel<<<(EE + 255) / 256, 256>>>(ei);
    sea_kernel<<<NN, EC>>>(ea);

    dim3 gg(HID / 64, (NN + 127) / 128);

    // layer 1
    agg_kernel<IN_C, false><<<NN, IN_C>>>(x);
    gemm3_kernel<IN_C, false><<<gg, 256>>>(x, W1, b1, 0);
    bn_kernel<<<(NN * HID / 4 + 255) / 256, 256>>>(g1, be1, 0);

    // layer 2
    agg_kernel<HID, true><<<NN, HID>>>(nullptr);
    gemm3_kernel<HID, true><<<gg, 256>>>(nullptr, W2, b2, 1);
    bn_kernel<<<(NN * HID / 4 + 255) / 256, 256>>>(g2, be2, 1);

    // layer 3 (BN fused into mlp pooling)
    agg_kernel<HID, true><<<NN, HID>>>(nullptr);
    gemm3_kernel<HID, true><<<gg, 256>>>(nullptr, W3, b3, 2);

    mlp_kernel<<<BB, MLPD>>>(batch, neighbor, g3, be3, fc1w, fc1b, fc2w, fc2b, out);
}

// round 6
// speedup vs baseline: 2.0167x; 2.0167x over previous
#include <cuda_runtime.h>
#include <cuda_bf16.h>
#include <cstdint>

// Problem constants
#define NN    10000
#define EE    320000
#define BB    64
#define IN_C  128
#define EC    64
#define HID   256
#define MLPD  512
#define NCO   4
#define K1    320
#define K23   576
#define EPSV  1e-5f
#define MAXSZ 40.0f
#define PADROWS 128
#define LSTR  (HID * K23)   // per-layer B image stride (elements)

// ---------------- scratch ----------------
__device__ int   g_deg[NN];
__device__ int   g_off[NN + 2];
__device__ int   g_cur[NN];
__device__ int   g_src[EE];
__device__ int   g_eid[EE];
__device__ __align__(16) float g_Sea[NN * EC];
__device__ __align__(16) float g_h[NN * HID];     // post-BN activation
__device__ __align__(16) float g_hp[NN * HID];    // post-relu pre-BN
__device__ float g_stats3[3 * 2 * HID];
__device__ __align__(16) __nv_bfloat16 g_Ahi[(NN + PADROWS) * K23];
__device__ __align__(16) __nv_bfloat16 g_Alo[(NN + PADROWS) * K23];
__device__ __align__(16) __nv_bfloat16 g_Bhi[3 * LSTR];   // [layer][n 256][k K] hi
__device__ __align__(16) __nv_bfloat16 g_Blo[3 * LSTR];   // lo

// ---------------- helpers ----------------
__device__ __forceinline__ uint32_t smem_u32(const void* p) {
    uint32_t a;
    asm("{ .reg .u64 t; cvta.to.shared.u64 t, %1; cvt.u32.u64 %0, t; }" : "=r"(a) : "l"(p));
    return a;
}
__device__ __forceinline__ void ldsm4(uint32_t* r, uint32_t addr) {
    asm volatile("ldmatrix.sync.aligned.m8n8.x4.shared.b16 {%0,%1,%2,%3}, [%4];"
                 : "=r"(r[0]), "=r"(r[1]), "=r"(r[2]), "=r"(r[3]) : "r"(addr));
}
__device__ __forceinline__ void mma_bf16(float* c, const uint32_t* a, const uint32_t* b) {
    asm volatile(
        "mma.sync.aligned.m16n8k16.row.col.f32.bf16.bf16.f32 "
        "{%0,%1,%2,%3}, {%4,%5,%6,%7}, {%8,%9}, {%0,%1,%2,%3};\n"
        : "+f"(c[0]), "+f"(c[1]), "+f"(c[2]), "+f"(c[3])
        : "r"(a[0]), "r"(a[1]), "r"(a[2]), "r"(a[3]), "r"(b[0]), "r"(b[1]));
}
__device__ __forceinline__ void split_store(__nv_bfloat16* hi, __nv_bfloat16* lo, float x) {
    __nv_bfloat16 h = __float2bfloat16(x);
    *hi = h;
    *lo = __float2bfloat16(x - __bfloat162float(h));
}

// ---------------- init ----------------
__global__ void zero_init_kernel() {
    int i = blockIdx.x * blockDim.x + threadIdx.x;
    if (i < NN) g_deg[i] = 0;
    if (i < 3 * 2 * HID) g_stats3[i] = 0.f;
    __nv_bfloat16 z = __float2bfloat16(0.f);
    if (i < PADROWS * K1) {
        g_Ahi[(size_t)NN * K1 + i] = z;
        g_Alo[(size_t)NN * K1 + i] = z;
    }
    if (i < PADROWS * K23) {
        g_Ahi[(size_t)NN * K23 + i] = z;
        g_Alo[(size_t)NN * K23 + i] = z;
    }
}

// ---------------- CSR build ----------------
__global__ void hist_kernel(const int* __restrict__ ei) {
    int e = blockIdx.x * blockDim.x + threadIdx.x;
    if (e < EE) atomicAdd(&g_deg[ei[EE + e]], 1);
}

__global__ void scan_kernel() {
    const int CH = 10;
    int tid = threadIdx.x;
    int base = tid * CH;
    int local[CH];
    int s = 0;
#pragma unroll
    for (int i = 0; i < CH; i++) {
        int idx = base + i;
        int v = (idx < NN) ? g_deg[idx] : 0;
        local[i] = s;
        s += v;
    }
    __shared__ int sh[1024];
    sh[tid] = s;
    __syncthreads();
    for (int d = 1; d < 1024; d <<= 1) {
        int t = (tid >= d) ? sh[tid - d] : 0;
        __syncthreads();
        sh[tid] += t;
        __syncthreads();
    }
    int excl = sh[tid] - s;
#pragma unroll
    for (int i = 0; i < CH; i++) {
        int idx = base + i;
        if (idx < NN) {
            int o = excl + local[i];
            g_off[idx] = o;
            g_cur[idx] = o;
        }
    }
    if (tid == 0) { g_off[NN] = EE; g_off[NN + 1] = EE; }
}

__global__ void fill_kernel(const int* __restrict__ ei) {
    int e = blockIdx.x * blockDim.x + threadIdx.x;
    if (e < EE) {
        int s = ei[e];
        int d = ei[EE + e];
        int pos = atomicAdd(&g_cur[d], 1);
        g_src[pos] = s;
        g_eid[pos] = e;
    }
}

// ---------------- Sea ----------------
__global__ void sea_kernel(const float* __restrict__ ea) {
    int v = blockIdx.x;
    int t = threadIdx.x;
    int s0 = g_off[v], s1 = g_off[v + 1];
    float acc = 1.0f;
    for (int j = s0; j < s1; j++) acc += ea[g_eid[j] * EC + t];
    g_Sea[v * EC + t] = acc;
}

// ---------------- aggregation + bf16 split A write ----------------
template <int D, int K, bool USE_G>
__global__ void aggprep_kernel(const float* __restrict__ xin) {
    const float* __restrict__ hin = USE_G ? (const float*)g_h : xin;
    int v = blockIdx.x;
    int t = threadIdx.x;
    int s0 = g_off[v], s1 = g_off[v + 1];
    float self = hin[v * D + t];
    float acc = self;
    int j = s0;
    for (; j + 4 <= s1; j += 4) {
        int a = g_src[j], b = g_src[j + 1], c = g_src[j + 2], d = g_src[j + 3];
        acc += hin[a * D + t] + hin[b * D + t] + hin[c * D + t] + hin[d * D + t];
    }
    for (; j < s1; j++) acc += hin[g_src[j] * D + t];

    float degf = (float)(s1 - s0 + 1);
    size_t rb = (size_t)v * K;
    split_store(&g_Ahi[rb + t], &g_Alo[rb + t], degf * self);
    split_store(&g_Ahi[rb + D + t], &g_Alo[rb + D + t], acc);
    if (t < EC) split_store(&g_Ahi[rb + 2 * D + t], &g_Alo[rb + 2 * D + t], g_Sea[v * EC + t]);
}

// ---------------- W prep: B = W^T, [n][k] k-major, bf16 split ----------------
__global__ void wprep_kernel(const float* __restrict__ W1, const float* __restrict__ W2,
                             const float* __restrict__ W3) {
    int l = blockIdx.y;
    int K = (l == 0) ? K1 : K23;
    const float* W = (l == 0) ? W1 : (l == 1) ? W2 : W3;
    int idx = blockIdx.x * 256 + threadIdx.x;
    if (idx >= HID * K) return;
    int n = idx / K;
    int k = idx - n * K;
    float v = W[(size_t)k * HID + n];
    __nv_bfloat16 h = __float2bfloat16(v);
    g_Bhi[(size_t)l * LSTR + idx] = h;
    g_Blo[(size_t)l * LSTR + idx] = __float2bfloat16(v - __bfloat162float(h));
}

// ---------------- bf16-split HMMA GEMM: g_hp = relu(A @ W + deg*b), fused stats ----------------
// BM=128, BN=64, BK=32. 256 threads, warps 4x2 (warp tile 32x32).
// SMEM stage: Ahi 8K | Alo 8K | Bhi 4K | Blo 4K = 24K, double-buffered = 48K dyn (opt-in set).
// Swizzle: 16B chunk of (row, seg) at row*64 + ((seg ^ ((row>>1)&3))<<4).
template <int K, int NCH>
__global__ __launch_bounds__(256, 2) void bf16gemm_kernel(int layer,
                                                          const float* __restrict__ bias) {
    extern __shared__ __align__(16) char smbuf[];
    const int STG = 24576;
    __shared__ float s_bias[64], s_deg[128], s_sum[64], s_sq[64];

    int tid = threadIdx.x;
    int lane = tid & 31;
    int wid = tid >> 5;
    int wm = wid >> 1;   // 0..3
    int wn = wid & 1;    // 0..1
    int rowBase = blockIdx.y * 128;
    int colBase = blockIdx.x * 64;

    if (tid < 128) {
        int r = rowBase + tid;
        s_deg[tid] = (r < NN) ? (float)(g_off[r + 1] - g_off[r] + 1) : 0.f;
    }
    if (tid < 64) {
        s_bias[tid] = bias[colBase + tid];
        s_sum[tid] = 0.f;
        s_sq[tid] = 0.f;
    }

    uint32_t smb = smem_u32(smbuf);

    const __nv_bfloat16* __restrict__ Agh = g_Ahi;
    const __nv_bfloat16* __restrict__ Agl = g_Alo;
    const __nv_bfloat16* __restrict__ Bgh = g_Bhi + (size_t)layer * LSTR;
    const __nv_bfloat16* __restrict__ Bgl = g_Blo + (size_t)layer * LSTR;

    // A load map: thread -> row = tid/2, 2 segs starting at (tid&1)*2
    int arow = tid >> 1;
    int at2 = tid & 1;
    size_t aoffBase = (size_t)(rowBase + arow) * K + at2 * 16;
    uint32_t asw0 = (uint32_t)arow * 64 + (((at2 * 2) ^ ((arow >> 1) & 3)) << 4);
    uint32_t asw1 = (uint32_t)arow * 64 + (((at2 * 2 + 1) ^ ((arow >> 1) & 3)) << 4);
    // B load map: thread -> row(n) = tid/4, seg = tid&3
    int brow = tid >> 2;
    int bseg = tid & 3;
    size_t boffBase = (size_t)(colBase + brow) * K + bseg * 8;
    uint32_t bsw = 16384u + (uint32_t)brow * 64 + ((bseg ^ ((brow >> 1) & 3)) << 4);

    float acc[2][4][4];
#pragma unroll
    for (int i = 0; i < 2; i++)
#pragma unroll
        for (int j = 0; j < 4; j++)
#pragma unroll
            for (int q = 0; q < 4; q++) acc[i][j][q] = 0.f;

    // prologue: chunk 0 -> buf0
    {
        uint4 a0 = *(const uint4*)(Agh + aoffBase);
        uint4 a1 = *(const uint4*)(Agh + aoffBase + 8);
        uint4 l0 = *(const uint4*)(Agl + aoffBase);
        uint4 l1 = *(const uint4*)(Agl + aoffBase + 8);
        uint4 b0 = *(const uint4*)(Bgh + boffBase);
        uint4 b1 = *(const uint4*)(Bgl + boffBase);
        *(uint4*)(smbuf + asw0) = a0;
        *(uint4*)(smbuf + asw1) = a1;
        *(uint4*)(smbuf + 8192 + asw0) = l0;
        *(uint4*)(smbuf + 8192 + asw1) = l1;
        *(uint4*)(smbuf + bsw) = b0;
        *(uint4*)(smbuf + 4096 + bsw) = b1;
    }
    __syncthreads();

    // frag address components
    int ra = wm * 32 + (lane & 7) + ((lane >> 3) & 1) * 8;
    int rb = wn * 32 + (lane & 7) + ((lane >> 4) & 1) * 8;

    for (int c = 0; c < NCH; c++) {
        uint4 na0, na1, nl0, nl1, nb0, nb1;
        if (c + 1 < NCH) {
            size_t ao = aoffBase + (size_t)(c + 1) * 32;
            size_t bo = boffBase + (size_t)(c + 1) * 32;
            na0 = *(const uint4*)(Agh + ao);
            na1 = *(const uint4*)(Agh + ao + 8);
            nl0 = *(const uint4*)(Agl + ao);
            nl1 = *(const uint4*)(Agl + ao + 8);
            nb0 = *(const uint4*)(Bgh + bo);
            nb1 = *(const uint4*)(Bgl + bo);
        }

        uint32_t base = smb + (uint32_t)(c & 1) * STG;
#pragma unroll
        for (int ks = 0; ks < 2; ks++) {
            int sa = ks * 2 + (lane >> 4);
            int sb = ks * 2 + ((lane >> 3) & 1);
            uint32_t ah[2][4], al[2][4];
#pragma unroll
            for (int i = 0; i < 2; i++) {
                int rr = ra + i * 16;
                uint32_t off = (uint32_t)rr * 64 + ((sa ^ ((rr >> 1) & 3)) << 4);
                ldsm4(ah[i], base + off);
                ldsm4(al[i], base + 8192 + off);
            }
            uint32_t bh[4][2], bl[4][2];
#pragma unroll
            for (int p = 0; p < 2; p++) {
                int rr = rb + p * 16;
                uint32_t off = (uint32_t)rr * 64 + ((sb ^ ((rr >> 1) & 3)) << 4);
                uint32_t t4[4];
                ldsm4(t4, base + 16384 + off);
                bh[2 * p][0] = t4[0]; bh[2 * p][1] = t4[1];
                bh[2 * p + 1][0] = t4[2]; bh[2 * p + 1][1] = t4[3];
                ldsm4(t4, base + 20480 + off);
                bl[2 * p][0] = t4[0]; bl[2 * p][1] = t4[1];
                bl[2 * p + 1][0] = t4[2]; bl[2 * p + 1][1] = t4[3];
            }
#pragma unroll
            for (int i = 0; i < 2; i++)
#pragma unroll
                for (int j = 0; j < 4; j++) {
                    mma_bf16(acc[i][j], ah[i], bh[j]);
                    mma_bf16(acc[i][j], al[i], bh[j]);
                    mma_bf16(acc[i][j], ah[i], bl[j]);
                }
        }

        if (c + 1 < NCH) {
            char* d = smbuf + ((c + 1) & 1) * STG;
            *(uint4*)(d + asw0) = na0;
            *(uint4*)(d + asw1) = na1;
            *(uint4*)(d + 8192 + asw0) = nl0;
            *(uint4*)(d + 8192 + asw1) = nl1;
            *(uint4*)(d + bsw) = nb0;
            *(uint4*)(d + 4096 + bsw) = nb1;
            __syncthreads();
        }
    }

    // ---------- epilogue: bias + relu + store + stats ----------
    float ss0[4], ss1[4], qq0[4], qq1[4];
#pragma unroll
    for (int j = 0; j < 4; j++) { ss0[j] = ss1[j] = qq0[j] = qq1[j] = 0.f; }

    int mb = rowBase + wm * 32 + (lane >> 2);
#pragma unroll
    for (int i = 0; i < 2; i++) {
        int m0 = mb + i * 16;
        int m1 = m0 + 8;
        bool v0 = m0 < NN, v1 = m1 < NN;
        float d0 = s_deg[m0 - rowBase];
        float d1 = s_deg[m1 - rowBase];
#pragma unroll
        for (int j = 0; j < 4; j++) {
            int cl = wn * 32 + j * 8 + (lane & 3) * 2;
            float b0 = s_bias[cl], b1 = s_bias[cl + 1];
            float x0 = fmaxf(acc[i][j][0] + d0 * b0, 0.f);
            float x1 = fmaxf(acc[i][j][1] + d0 * b1, 0.f);
            float x2 = fmaxf(acc[i][j][2] + d1 * b0, 0.f);
            float x3 = fmaxf(acc[i][j][3] + d1 * b1, 0.f);
            if (v0) *(float2*)&g_hp[(size_t)m0 * HID + colBase + cl] = make_float2(x0, x1);
            if (v1) *(float2*)&g_hp[(size_t)m1 * HID + colBase + cl] = make_float2(x2, x3);
            float m00 = v0 ? x0 : 0.f, m01 = v0 ? x1 : 0.f;
            float m10 = v1 ? x2 : 0.f, m11 = v1 ? x3 : 0.f;
            ss0[j] += m00 + m10;
            ss1[j] += m01 + m11;
            qq0[j] += m00 * m00 + m10 * m10;
            qq1[j] += m01 * m01 + m11 * m11;
        }
    }
#pragma unroll
    for (int j = 0; j < 4; j++) {
#pragma unroll
        for (int o = 4; o < 32; o <<= 1) {
            ss0[j] += __shfl_xor_sync(0xffffffffu, ss0[j], o);
            ss1[j] += __shfl_xor_sync(0xffffffffu, ss1[j], o);
            qq0[j] += __shfl_xor_sync(0xffffffffu, qq0[j], o);
            qq1[j] += __shfl_xor_sync(0xffffffffu, qq1[j], o);
        }
        if (lane < 4) {
            int cl = wn * 32 + j * 8 + lane * 2;
            atomicAdd(&s_sum[cl], ss0[j]);
            atomicAdd(&s_sum[cl + 1], ss1[j]);
            atomicAdd(&s_sq[cl], qq0[j]);
            atomicAdd(&s_sq[cl + 1], qq1[j]);
        }
    }
    __syncthreads();
    if (tid < 64) {
        atomicAdd(&g_stats3[layer * 512 + colBase + tid], s_sum[tid]);
        atomicAdd(&g_stats3[layer * 512 + HID + colBase + tid], s_sq[tid]);
    }
}

// ---------------- BN apply + relu -> g_h ----------------
__global__ void bn_kernel(const float* __restrict__ gamma, const float* __restrict__ beta,
                          int layer) {
    int idx = blockIdx.x * blockDim.x + threadIdx.x;
    if (idx >= NN * HID / 4) return;
    int f = idx * 4;
    int c = f & (HID - 1);
    const float invN = 1.0f / (float)NN;
    float4 v = *(const float4*)&g_hp[f];
    float4 o;
#pragma unroll
    for (int e = 0; e < 4; e++) {
        int cc = c + e;
        float mu = g_stats3[layer * 512 + cc] * invN;
        float var = g_stats3[layer * 512 + HID + cc] * invN - mu * mu;
        float rs = rsqrtf(var + EPSV);
        float val = ((&v.x)[e] - mu) * rs * gamma[cc] + beta[cc];
        (&o.x)[e] = fmaxf(val, 0.f);
    }
    *(float4*)&g_h[f] = o;
}

// ---------------- fused layer-3 BN + pooling + MLP ----------------
__device__ __forceinline__ int lower_bound_dev(const int* a, int n, int key) {
    int lo = 0, hi = n;
    while (lo < hi) {
        int m = (lo + hi) >> 1;
        if (a[m] < key) lo = m + 1; else hi = m;
    }
    return lo;
}

__global__ __launch_bounds__(512) void mlp_kernel(const int* __restrict__ batch,
                                                  const float* __restrict__ neighbor,
                                                  const float* __restrict__ g3,
                                                  const float* __restrict__ be3,
                                                  const float* __restrict__ fc1w,
                                                  const float* __restrict__ fc1b,
                                                  const float* __restrict__ fc2w,
                                                  const float* __restrict__ fc2b,
                                                  float* __restrict__ out) {
    const int ZD = HID + 1 + IN_C;  // 385
    __shared__ float z[ZD];
    __shared__ float part[512];
    __shared__ float red[NCO];
    int b = blockIdx.x;
    int t = threadIdx.x;

    int lo = lower_bound_dev(batch, NN, b);
    int hi = lower_bound_dev(batch, NN, b + 1);

    {
        int c = t & 255;
        int half = t >> 8;
        const float invN = 1.0f / (float)NN;
        float mu = g_stats3[2 * 512 + c] * invN;
        float var = g_stats3[2 * 512 + HID + c] * invN - mu * mu;
        float rs = rsqrtf(var + EPSV);
        float sc = g3[c] * rs;
        float off = be3[c] - mu * sc;
        float s = 0.f;
        for (int r = lo + half; r < hi; r += 2)
            s += fmaxf(g_hp[(size_t)r * HID + c] * sc + off, 0.f);
        part[t] = s;
    }
    __syncthreads();
    if (t < HID) z[t] = part[t] + part[t + 256];
    else if (t == HID) z[HID] = (float)(hi - lo) / MAXSZ;
    else if (t > HID && t < HID + 1 + IN_C + 1) {
        int k = t - HID - 1;
        if (k < IN_C) z[HID + 1 + k] = neighbor[b * IN_C + k];
    }
    if (t < NCO) red[t] = fc2b[t];
    __syncthreads();

    float acc = fc1b[t];
#pragma unroll 4
    for (int k = 0; k < ZD; k++) acc += z[k] * fc1w[k * MLPD + t];
    float h1 = fmaxf(acc, 0.f);

    float4 w4 = *(const float4*)&fc2w[t * NCO];
    float p0 = h1 * w4.x, p1 = h1 * w4.y, p2 = h1 * w4.z, p3 = h1 * w4.w;
#pragma unroll
    for (int o = 16; o >= 1; o >>= 1) {
        p0 += __shfl_xor_sync(0xffffffffu, p0, o);
        p1 += __shfl_xor_sync(0xffffffffu, p1, o);
        p2 += __shfl_xor_sync(0xffffffffu, p2, o);
        p3 += __shfl_xor_sync(0xffffffffu, p3, o);
    }
    if ((t & 31) == 0) {
        atomicAdd(&red[0], p0);
        atomicAdd(&red[1], p1);
        atomicAdd(&red[2], p2);
        atomicAdd(&red[3], p3);
    }
    __syncthreads();
    if (t < NCO) out[b * NCO + t] = red[t];
}

// ---------------- launch ----------------
extern "C" void kernel_launch(void* const* d_in, const int* in_sizes, int n_in,
                              void* d_out, int out_size) {
    const float* x        = (const float*)d_in[0];
    const int*   ei       = (const int*)d_in[1];
    const float* ea       = (const float*)d_in[2];
    const int*   batch    = (const int*)d_in[3];
    const float* neighbor = (const float*)d_in[4];
    const float* W1  = (const float*)d_in[5];
    const float* b1  = (const float*)d_in[6];
    const float* g1  = (const float*)d_in[7];
    const float* be1 = (const float*)d_in[8];
    const float* W2  = (const float*)d_in[9];
    const float* b2  = (const float*)d_in[10];
    const float* g2  = (const float*)d_in[11];
    const float* be2 = (const float*)d_in[12];
    const float* W3  = (const float*)d_in[13];
    const float* b3  = (const float*)d_in[14];
    const float* g3  = (const float*)d_in[15];
    const float* be3 = (const float*)d_in[16];
    const float* fc1w = (const float*)d_in[17];
    const float* fc1b = (const float*)d_in[18];
    const float* fc2w = (const float*)d_in[19];
    const float* fc2b = (const float*)d_in[20];
    float* out = (float*)d_out;

    // Opt in to >48KB total smem (49152 dyn + ~1.3KB static). Unconditional:
    // host-side non-stream API, legal during graph capture, deterministic.
    cudaFuncSetAttribute(bf16gemm_kernel<K1, 10>,
                         cudaFuncAttributeMaxDynamicSharedMemorySize, 49152);
    cudaFuncSetAttribute(bf16gemm_kernel<K23, 18>,
                         cudaFuncAttributeMaxDynamicSharedMemorySize, 49152);

    zero_init_kernel<<<(PADROWS * K23 + 255) / 256, 256>>>();
    hist_kernel<<<(EE + 255) / 256, 256>>>(ei);
    scan_kernel<<<1, 1024>>>();
    fill_kernel<<<(EE + 255) / 256, 256>>>(ei);
    sea_kernel<<<NN, EC>>>(ea);
    {
        dim3 wg((HID * K23 + 255) / 256, 3);  // (576, 3)
        wprep_kernel<<<wg, 256>>>(W1, W2, W3);
    }

    dim3 gg(4, 79);                // N/64 col blocks x M/128 row blocks
    const size_t dsm = 49152;      // 48KB double-buffered stage

    // layer 1
    aggprep_kernel<IN_C, K1, false><<<NN, IN_C>>>(x);
    bf16gemm_kernel<K1, 10><<<gg, 256, dsm>>>(0, b1);
    bn_kernel<<<(NN * HID / 4 + 255) / 256, 256>>>(g1, be1, 0);

    // layer 2
    aggprep_kernel<HID, K23, true><<<NN, HID>>>(nullptr);
    bf16gemm_kernel<K23, 18><<<gg, 256, dsm>>>(1, b2);
    bn_kernel<<<(NN * HID / 4 + 255) / 256, 256>>>(g2, be2, 1);

    // layer 3 (BN fused into mlp)
    aggprep_kernel<HID, K23, true><<<NN, HID>>>(nullptr);
    bf16gemm_kernel<K23, 18><<<gg, 256, dsm>>>(2, b3);

    mlp_kernel<<<BB, MLPD>>>(batch, neighbor, g3, be3, fc1w, fc1b, fc2w, fc2b, out);
}